// round 5
// baseline (speedup 1.0000x reference)
#include <cuda_runtime.h>
#include <math.h>

#define N_NODES 50000
#define N_EDGES 800000
#define D 128
#define ALPHA 0.2f

// ---------------- scratch (static device globals; no allocation) ------------
__device__ float g_h[N_NODES * D];          // 25.6 MB
__device__ float g_s1[N_NODES];
__device__ float g_s2[N_NODES];
__device__ float g_e[N_EDGES];              // edge score, later exp(e-max)
__device__ int   g_src[N_EDGES];
__device__ int   g_dst[N_EDGES];
__device__ float g_pmax[4096];
__device__ float g_psum[4096];
__device__ float g_max;
__device__ float g_invsum;
__device__ int   g_is32;                    // 1 if edge_index is int32

static constexpr int EBLK = 256;
static constexpr int NEB  = (N_EDGES + EBLK - 1) / EBLK;   // 3125 partials

// ---------------- 0a: zero output + detect flag init -------------------------
__global__ void k_zero(float* __restrict__ out) {
    int i = blockIdx.x * 1024 + threadIdx.x;
    if (i < N_NODES * D) out[i] = 0.0f;
    if (i == 0) g_is32 = 0;
}

// ---------------- 0b: detect int32 vs int64 edge_index -----------------------
// If int64 (LE) with values < 2^31, every odd 32-bit word is 0.
// If int32 random indices, many odd words are nonzero.
__global__ __launch_bounds__(256) void k_detect(const int* __restrict__ p32) {
    int i = blockIdx.x * 256 + threadIdx.x;           // odd word index = 2i+1
    int w = (2 * i + 1 < 2 * N_EDGES) ? p32[2 * i + 1] : 0;
    if (__syncthreads_or(w != 0) && threadIdx.x == 0) g_is32 = 1;
}

// ---------------- 0c: decode src/dst to int32 --------------------------------
__global__ __launch_bounds__(256) void k_decode(const int* __restrict__ p32) {
    int i = blockIdx.x * 256 + threadIdx.x;
    if (i >= N_EDGES) return;
    if (g_is32) {
        g_src[i] = p32[i];
        g_dst[i] = p32[N_EDGES + i];
    } else {                                          // int64: low word of each
        g_src[i] = p32[2 * i];
        g_dst[i] = p32[2 * (N_EDGES + i)];
    }
}

// ---------------- 1: h = x @ W  (fp32, smem X tile, W via L1) ----------------
__global__ __launch_bounds__(256) void k_gemm(const float* __restrict__ x,
                                              const float* __restrict__ W) {
    __shared__ float Xs[64 * 128];   // 32 KB
    const int row0 = blockIdx.x * 64;

    for (int i = threadIdx.x; i < 64 * 128; i += 256) {
        int r = row0 + (i >> 7);
        Xs[i] = (r < N_NODES) ? x[(size_t)r * 128 + (i & 127)] : 0.0f;
    }
    __syncthreads();

    const int col = threadIdx.x & 127;
    const int rh  = threadIdx.x >> 7;        // 0 or 1

    float acc[32];
#pragma unroll
    for (int i = 0; i < 32; i++) acc[i] = 0.0f;

    for (int k = 0; k < 128; k += 4) {
        float w0 = __ldg(&W[(k + 0) * 128 + col]);
        float w1 = __ldg(&W[(k + 1) * 128 + col]);
        float w2 = __ldg(&W[(k + 2) * 128 + col]);
        float w3 = __ldg(&W[(k + 3) * 128 + col]);
#pragma unroll
        for (int i = 0; i < 32; i++) {
            const float4 xv = *(const float4*)&Xs[(rh * 32 + i) * 128 + k];
            acc[i] = fmaf(xv.x, w0, acc[i]);
            acc[i] = fmaf(xv.y, w1, acc[i]);
            acc[i] = fmaf(xv.z, w2, acc[i]);
            acc[i] = fmaf(xv.w, w3, acc[i]);
        }
    }

#pragma unroll
    for (int i = 0; i < 32; i++) {
        int gr = row0 + rh * 32 + i;
        if (gr < N_NODES) g_h[(size_t)gr * 128 + col] = acc[i];
    }
}

// ---------------- 2: s1 = h@a1, s2 = h@a2  (warp per node) -------------------
__global__ __launch_bounds__(256) void k_scores(const float* __restrict__ a) {
    int gw   = (blockIdx.x * 256 + threadIdx.x) >> 5;
    int lane = threadIdx.x & 31;
    if (gw >= N_NODES) return;

    const float4 hv = *(const float4*)&g_h[(size_t)gw * 128 + lane * 4];
    const float4 a1 = *(const float4*)&a[lane * 4];
    const float4 a2 = *(const float4*)&a[128 + lane * 4];

    float p1 = hv.x * a1.x + hv.y * a1.y + hv.z * a1.z + hv.w * a1.w;
    float p2 = hv.x * a2.x + hv.y * a2.y + hv.z * a2.z + hv.w * a2.w;
#pragma unroll
    for (int s = 16; s > 0; s >>= 1) {
        p1 += __shfl_xor_sync(0xFFFFFFFFu, p1, s);
        p2 += __shfl_xor_sync(0xFFFFFFFFu, p2, s);
    }
    if (lane == 0) { g_s1[gw] = p1; g_s2[gw] = p2; }
}

// ---------------- 3: e = leaky_relu(s1[src]+s2[dst]); per-block max ----------
__global__ __launch_bounds__(EBLK) void k_edge_e() {
    __shared__ float sm[EBLK];
    int i = blockIdx.x * EBLK + threadIdx.x;
    float v = -1e30f;
    if (i < N_EDGES) {
        int s = g_src[i];
        int d = g_dst[i];
        float t = g_s1[s] + g_s2[d];
        v = (t > 0.0f) ? t : ALPHA * t;
        g_e[i] = v;
    }
    sm[threadIdx.x] = v;
    __syncthreads();
    for (int s = EBLK / 2; s > 0; s >>= 1) {
        if (threadIdx.x < s) sm[threadIdx.x] = fmaxf(sm[threadIdx.x], sm[threadIdx.x + s]);
        __syncthreads();
    }
    if (threadIdx.x == 0) g_pmax[blockIdx.x] = sm[0];
}

// ---------------- 4: reduce block maxima -> g_max ----------------------------
__global__ __launch_bounds__(1024) void k_reduce_max() {
    __shared__ float sm[1024];
    float m = -1e30f;
    for (int i = threadIdx.x; i < NEB; i += 1024) m = fmaxf(m, g_pmax[i]);
    sm[threadIdx.x] = m;
    __syncthreads();
    for (int s = 512; s > 0; s >>= 1) {
        if (threadIdx.x < s) sm[threadIdx.x] = fmaxf(sm[threadIdx.x], sm[threadIdx.x + s]);
        __syncthreads();
    }
    if (threadIdx.x == 0) g_max = sm[0];
}

// ---------------- 5: g_e <- exp(e - max); per-block sum ----------------------
__global__ __launch_bounds__(EBLK) void k_expsum() {
    __shared__ float sm[EBLK];
    int i = blockIdx.x * EBLK + threadIdx.x;
    float v = 0.0f;
    if (i < N_EDGES) {
        v = expf(g_e[i] - g_max);
        g_e[i] = v;
    }
    sm[threadIdx.x] = v;
    __syncthreads();
    for (int s = EBLK / 2; s > 0; s >>= 1) {
        if (threadIdx.x < s) sm[threadIdx.x] += sm[threadIdx.x + s];
        __syncthreads();
    }
    if (threadIdx.x == 0) g_psum[blockIdx.x] = sm[0];
}

// ---------------- 6: reduce block sums -> g_invsum ---------------------------
__global__ __launch_bounds__(1024) void k_reduce_sum() {
    __shared__ float sm[1024];
    float m = 0.0f;
    for (int i = threadIdx.x; i < NEB; i += 1024) m += g_psum[i];
    sm[threadIdx.x] = m;
    __syncthreads();
    for (int s = 512; s > 0; s >>= 1) {
        if (threadIdx.x < s) sm[threadIdx.x] += sm[threadIdx.x + s];
        __syncthreads();
    }
    if (threadIdx.x == 0) g_invsum = 1.0f / sm[0];
}

// ---------------- 7: out[dst] += att * h[src]  (warp per edge) ---------------
__global__ __launch_bounds__(256) void k_scatter(float* __restrict__ out) {
    const int warp = threadIdx.x >> 5;
    const int lane = threadIdx.x & 31;
    const int i = blockIdx.x * 8 + warp;
    if (i >= N_EDGES) return;

    const float att = g_e[i] * g_invsum;
    const int s = g_src[i];
    const int d = g_dst[i];

    const float4 v = *(const float4*)&g_h[(size_t)s * 128 + lane * 4];
    float* o = out + (size_t)d * 128 + lane * 4;
    // return value unused -> ptxas emits RED.E.ADD.F32 (no round trip)
    atomicAdd(o + 0, att * v.x);
    atomicAdd(o + 1, att * v.y);
    atomicAdd(o + 2, att * v.z);
    atomicAdd(o + 3, att * v.w);
}

// ---------------- launch -----------------------------------------------------
extern "C" void kernel_launch(void* const* d_in, const int* in_sizes, int n_in,
                              void* d_out, int out_size) {
    const float* x = nullptr;
    const float* W = nullptr;
    const float* a = nullptr;
    const int*   ei = nullptr;
    for (int i = 0; i < n_in; i++) {
        if (in_sizes[i] == N_NODES * D)      x  = (const float*)d_in[i];
        else if (in_sizes[i] == D * D)       W  = (const float*)d_in[i];
        else if (in_sizes[i] == 2 * D)       a  = (const float*)d_in[i];
        else if (in_sizes[i] == 2 * N_EDGES) ei = (const int*)d_in[i];
    }
    float* out = (float*)d_out;

    k_zero<<<(N_NODES * D + 1023) / 1024, 1024>>>(out);
    k_detect<<<(N_EDGES + 255) / 256, 256>>>(ei);
    k_decode<<<(N_EDGES + 255) / 256, 256>>>(ei);
    k_gemm<<<(N_NODES + 63) / 64, 256>>>(x, W);
    k_scores<<<(N_NODES * 32 + 255) / 256, 256>>>(a);
    k_edge_e<<<NEB, EBLK>>>();
    k_reduce_max<<<1, 1024>>>();
    k_expsum<<<NEB, EBLK>>>();
    k_reduce_sum<<<1, 1024>>>();
    k_scatter<<<(N_EDGES + 7) / 8, 256>>>(out);
}

// round 10
// speedup vs baseline: 1.5099x; 1.5099x over previous
#include <cuda_runtime.h>
#include <math.h>

#define N_NODES 50000
#define N_EDGES 800000
#define D 128
#define ALPHA 0.2f

// ---------------- scratch (static device globals; no allocation) ------------
__device__ float g_h[N_NODES * D];          // 25.6 MB
__device__ float g_s1[N_NODES];
__device__ float g_s2[N_NODES];
__device__ float g_e[N_EDGES];              // edge score, later exp(e-max)
__device__ int   g_src[N_EDGES];
__device__ int   g_dst[N_EDGES];
__device__ int   g_deg[N_NODES];
__device__ int   g_off[N_NODES];
__device__ int   g_cursor[N_NODES];
__device__ int2  g_csr[N_EDGES];            // {src, float_bits(exp_e)} per dst bucket
__device__ float g_pmax[4096];
__device__ float g_psum[4096];
__device__ float g_max;
__device__ float g_invsum;
__device__ int   g_is32;                    // 1 if edge_index is int32

static constexpr int EBLK = 256;
static constexpr int NEB  = (N_EDGES + EBLK - 1) / EBLK;   // 3125 partials

// ---------------- 0a: init counters ------------------------------------------
__global__ void k_init() {
    int i = blockIdx.x * 1024 + threadIdx.x;
    if (i < N_NODES) g_deg[i] = 0;
    if (i == 0) g_is32 = 0;
}

// ---------------- 0b: detect int32 vs int64 edge_index -----------------------
// If int64 (LE) with values < 2^31, every odd 32-bit word is 0.
__global__ __launch_bounds__(256) void k_detect(const int* __restrict__ p32) {
    int i = blockIdx.x * 256 + threadIdx.x;           // odd word index = 2i+1
    int w = (2 * i + 1 < 2 * N_EDGES) ? p32[2 * i + 1] : 0;
    if (__syncthreads_or(w != 0) && threadIdx.x == 0) g_is32 = 1;
}

// ---------------- 0c: decode src/dst to int32 + count dst degrees ------------
__global__ __launch_bounds__(256) void k_decode(const int* __restrict__ p32) {
    int i = blockIdx.x * 256 + threadIdx.x;
    if (i >= N_EDGES) return;
    int s, d;
    if (g_is32) {
        s = p32[i];
        d = p32[N_EDGES + i];
    } else {                                          // int64: low word of each
        s = p32[2 * i];
        d = p32[2 * (N_EDGES + i)];
    }
    g_src[i] = s;
    g_dst[i] = d;
    atomicAdd(&g_deg[d], 1);                          // RED (no return)
}

// ---------------- 1: h = x @ W  (fp32, smem X tile, W via L1) ----------------
__global__ __launch_bounds__(256) void k_gemm(const float* __restrict__ x,
                                              const float* __restrict__ W) {
    __shared__ float Xs[64 * 128];   // 32 KB
    const int row0 = blockIdx.x * 64;

    for (int i = threadIdx.x; i < 64 * 128; i += 256) {
        int r = row0 + (i >> 7);
        Xs[i] = (r < N_NODES) ? x[(size_t)r * 128 + (i & 127)] : 0.0f;
    }
    __syncthreads();

    const int col = threadIdx.x & 127;
    const int rh  = threadIdx.x >> 7;        // 0 or 1

    float acc[32];
#pragma unroll
    for (int i = 0; i < 32; i++) acc[i] = 0.0f;

    for (int k = 0; k < 128; k += 4) {
        float w0 = __ldg(&W[(k + 0) * 128 + col]);
        float w1 = __ldg(&W[(k + 1) * 128 + col]);
        float w2 = __ldg(&W[(k + 2) * 128 + col]);
        float w3 = __ldg(&W[(k + 3) * 128 + col]);
#pragma unroll
        for (int i = 0; i < 32; i++) {
            const float4 xv = *(const float4*)&Xs[(rh * 32 + i) * 128 + k];
            acc[i] = fmaf(xv.x, w0, acc[i]);
            acc[i] = fmaf(xv.y, w1, acc[i]);
            acc[i] = fmaf(xv.z, w2, acc[i]);
            acc[i] = fmaf(xv.w, w3, acc[i]);
        }
    }

#pragma unroll
    for (int i = 0; i < 32; i++) {
        int gr = row0 + rh * 32 + i;
        if (gr < N_NODES) g_h[(size_t)gr * 128 + col] = acc[i];
    }
}

// ---------------- 2: s1 = h@a1, s2 = h@a2  (warp per node) -------------------
__global__ __launch_bounds__(256) void k_scores(const float* __restrict__ a) {
    int gw   = (blockIdx.x * 256 + threadIdx.x) >> 5;
    int lane = threadIdx.x & 31;
    if (gw >= N_NODES) return;

    const float4 hv = *(const float4*)&g_h[(size_t)gw * 128 + lane * 4];
    const float4 a1 = *(const float4*)&a[lane * 4];
    const float4 a2 = *(const float4*)&a[128 + lane * 4];

    float p1 = hv.x * a1.x + hv.y * a1.y + hv.z * a1.z + hv.w * a1.w;
    float p2 = hv.x * a2.x + hv.y * a2.y + hv.z * a2.z + hv.w * a2.w;
#pragma unroll
    for (int s = 16; s > 0; s >>= 1) {
        p1 += __shfl_xor_sync(0xFFFFFFFFu, p1, s);
        p2 += __shfl_xor_sync(0xFFFFFFFFu, p2, s);
    }
    if (lane == 0) { g_s1[gw] = p1; g_s2[gw] = p2; }
}

// ---------------- 3: e = leaky_relu(s1[src]+s2[dst]); per-block max ----------
__global__ __launch_bounds__(EBLK) void k_edge_e() {
    __shared__ float sm[EBLK];
    int i = blockIdx.x * EBLK + threadIdx.x;
    float v = -1e30f;
    if (i < N_EDGES) {
        int s = g_src[i];
        int d = g_dst[i];
        float t = g_s1[s] + g_s2[d];
        v = (t > 0.0f) ? t : ALPHA * t;
        g_e[i] = v;
    }
    sm[threadIdx.x] = v;
    __syncthreads();
    for (int s = EBLK / 2; s > 0; s >>= 1) {
        if (threadIdx.x < s) sm[threadIdx.x] = fmaxf(sm[threadIdx.x], sm[threadIdx.x + s]);
        __syncthreads();
    }
    if (threadIdx.x == 0) g_pmax[blockIdx.x] = sm[0];
}

// ---------------- 4: reduce block maxima -> g_max ----------------------------
__global__ __launch_bounds__(1024) void k_reduce_max() {
    __shared__ float sm[1024];
    float m = -1e30f;
    for (int i = threadIdx.x; i < NEB; i += 1024) m = fmaxf(m, g_pmax[i]);
    sm[threadIdx.x] = m;
    __syncthreads();
    for (int s = 512; s > 0; s >>= 1) {
        if (threadIdx.x < s) sm[threadIdx.x] = fmaxf(sm[threadIdx.x], sm[threadIdx.x + s]);
        __syncthreads();
    }
    if (threadIdx.x == 0) g_max = sm[0];
}

// ---------------- 5: g_e <- exp(e - max); per-block sum ----------------------
__global__ __launch_bounds__(EBLK) void k_expsum() {
    __shared__ float sm[EBLK];
    int i = blockIdx.x * EBLK + threadIdx.x;
    float v = 0.0f;
    if (i < N_EDGES) {
        v = expf(g_e[i] - g_max);
        g_e[i] = v;
    }
    sm[threadIdx.x] = v;
    __syncthreads();
    for (int s = EBLK / 2; s > 0; s >>= 1) {
        if (threadIdx.x < s) sm[threadIdx.x] += sm[threadIdx.x + s];
        __syncthreads();
    }
    if (threadIdx.x == 0) g_psum[blockIdx.x] = sm[0];
}

// ---------------- 6: reduce block sums -> g_invsum ---------------------------
__global__ __launch_bounds__(1024) void k_reduce_sum() {
    __shared__ float sm[1024];
    float m = 0.0f;
    for (int i = threadIdx.x; i < NEB; i += 1024) m += g_psum[i];
    sm[threadIdx.x] = m;
    __syncthreads();
    for (int s = 512; s > 0; s >>= 1) {
        if (threadIdx.x < s) sm[threadIdx.x] += sm[threadIdx.x + s];
        __syncthreads();
    }
    if (threadIdx.x == 0) g_invsum = 1.0f / sm[0];
}

// ---------------- 7: exclusive scan of degrees -> offsets + cursors ----------
__global__ __launch_bounds__(1024) void k_scan() {
    __shared__ int sm[1024];
    __shared__ int s_carry;
    if (threadIdx.x == 0) s_carry = 0;
    __syncthreads();
    const int nchunk = (N_NODES + 1023) / 1024;      // 49
    for (int c = 0; c < nchunk; c++) {
        int i = c * 1024 + threadIdx.x;
        int v = (i < N_NODES) ? g_deg[i] : 0;
        sm[threadIdx.x] = v;
        __syncthreads();
        for (int s = 1; s < 1024; s <<= 1) {
            int t = (threadIdx.x >= s) ? sm[threadIdx.x - s] : 0;
            __syncthreads();
            sm[threadIdx.x] += t;
            __syncthreads();
        }
        int excl = sm[threadIdx.x] - v + s_carry;
        if (i < N_NODES) { g_off[i] = excl; g_cursor[i] = excl; }
        __syncthreads();
        if (threadIdx.x == 0) s_carry += sm[1023];
        __syncthreads();
    }
}

// ---------------- 8: permute edges into dst-sorted CSR -----------------------
__global__ __launch_bounds__(256) void k_permute() {
    int i = blockIdx.x * 256 + threadIdx.x;
    if (i >= N_EDGES) return;
    int d = g_dst[i];
    int pos = atomicAdd(&g_cursor[d], 1);
    int2 ent;
    ent.x = g_src[i];
    ent.y = __float_as_int(g_e[i]);                  // exp(e - max)
    g_csr[pos] = ent;
}

// ---------------- 9: gather  out[n] = invsum * sum_j p_j * h[src_j] ----------
// Warp per node; each output row written exactly once (no atomics, covers all nodes).
__global__ __launch_bounds__(256) void k_gather(float* __restrict__ out) {
    const int warp = threadIdx.x >> 5;
    const int lane = threadIdx.x & 31;
    const int node = blockIdx.x * 8 + warp;
    if (node >= N_NODES) return;

    const int beg = g_off[node];
    const int end = beg + g_deg[node];

    float ax = 0.f, ay = 0.f, az = 0.f, aw = 0.f;
    int j = beg;
    for (; j + 1 < end; j += 2) {                    // 2-way unroll for MLP
        const int2 e0 = g_csr[j];
        const int2 e1 = g_csr[j + 1];
        const float p0 = __int_as_float(e0.y);
        const float p1 = __int_as_float(e1.y);
        const float4 v0 = *(const float4*)&g_h[(size_t)e0.x * 128 + lane * 4];
        const float4 v1 = *(const float4*)&g_h[(size_t)e1.x * 128 + lane * 4];
        ax = fmaf(p0, v0.x, ax); ay = fmaf(p0, v0.y, ay);
        az = fmaf(p0, v0.z, az); aw = fmaf(p0, v0.w, aw);
        ax = fmaf(p1, v1.x, ax); ay = fmaf(p1, v1.y, ay);
        az = fmaf(p1, v1.z, az); aw = fmaf(p1, v1.w, aw);
    }
    if (j < end) {
        const int2 e0 = g_csr[j];
        const float p0 = __int_as_float(e0.y);
        const float4 v0 = *(const float4*)&g_h[(size_t)e0.x * 128 + lane * 4];
        ax = fmaf(p0, v0.x, ax); ay = fmaf(p0, v0.y, ay);
        az = fmaf(p0, v0.z, az); aw = fmaf(p0, v0.w, aw);
    }

    const float inv = g_invsum;
    float4 r; r.x = ax * inv; r.y = ay * inv; r.z = az * inv; r.w = aw * inv;
    *(float4*)&out[(size_t)node * 128 + lane * 4] = r;
}

// ---------------- launch -----------------------------------------------------
extern "C" void kernel_launch(void* const* d_in, const int* in_sizes, int n_in,
                              void* d_out, int out_size) {
    const float* x = nullptr;
    const float* W = nullptr;
    const float* a = nullptr;
    const int*   ei = nullptr;
    for (int i = 0; i < n_in; i++) {
        if (in_sizes[i] == N_NODES * D)      x  = (const float*)d_in[i];
        else if (in_sizes[i] == D * D)       W  = (const float*)d_in[i];
        else if (in_sizes[i] == 2 * D)       a  = (const float*)d_in[i];
        else if (in_sizes[i] == 2 * N_EDGES) ei = (const int*)d_in[i];
    }
    float* out = (float*)d_out;

    k_init<<<(N_NODES + 1023) / 1024, 1024>>>();
    k_detect<<<(N_EDGES + 255) / 256, 256>>>(ei);
    k_decode<<<(N_EDGES + 255) / 256, 256>>>(ei);
    k_gemm<<<(N_NODES + 63) / 64, 256>>>(x, W);
    k_scores<<<(N_NODES * 32 + 255) / 256, 256>>>(a);
    k_edge_e<<<NEB, EBLK>>>();
    k_reduce_max<<<1, 1024>>>();
    k_expsum<<<NEB, EBLK>>>();
    k_reduce_sum<<<1, 1024>>>();
    k_scan<<<1, 1024>>>();
    k_permute<<<(N_EDGES + 255) / 256, 256>>>();
    k_gather<<<(N_NODES + 7) / 8, 256>>>(out);
}

// round 12
// speedup vs baseline: 2.5520x; 1.6902x over previous
#include <cuda_runtime.h>
#include <math.h>

#define N_NODES 50000
#define N_EDGES 800000
#define D 128
#define ALPHA 0.2f

// ---------------- scratch (static device globals; no allocation) ------------
__device__ float g_h[N_NODES * D];          // 25.6 MB
__device__ float g_s1[N_NODES];
__device__ float g_s2[N_NODES];
__device__ float g_e[N_EDGES];              // exp(e - C)
__device__ int   g_src[N_EDGES];
__device__ int   g_dst[N_EDGES];
__device__ int   g_deg[N_NODES];
__device__ int   g_off[N_NODES];
__device__ int   g_cursor[N_NODES];
__device__ int2  g_csr[N_EDGES];            // {src, float_bits(p)} per dst bucket
__device__ int   g_bsum[64];
__device__ int   g_bexc[64];
__device__ float g_psum[4096];
__device__ float g_invsum;
__device__ int   g_m1enc;                   // encoded float max of s1
__device__ int   g_m2enc;                   // encoded float max of s2
__device__ int   g_is32;                    // 1 if edge_index is int32

static constexpr int EBLK = 256;
static constexpr int NEB  = (N_EDGES + EBLK - 1) / EBLK;   // 3125

// order-preserving float<->int encode (monotone for non-NaN)
__device__ __forceinline__ int   f_enc(float f) { int i = __float_as_int(f); return (i >= 0) ? i : (i ^ 0x7FFFFFFF); }
__device__ __forceinline__ float f_dec(int i)   { return __int_as_float((i >= 0) ? i : (i ^ 0x7FFFFFFF)); }

// ---------------- 0a: init counters ------------------------------------------
__global__ void k_init() {
    int i = blockIdx.x * 1024 + threadIdx.x;
    if (i < N_NODES) g_deg[i] = 0;
    if (i == 0) { g_is32 = 0; g_m1enc = f_enc(-1e30f); g_m2enc = f_enc(-1e30f); }
}

// ---------------- 0b: detect int32 vs int64 (sampled: first 64K odd words) ---
// int64 (LE) indices < 2^31 -> odd 32-bit words all zero; int32 random -> not.
__global__ __launch_bounds__(256) void k_detect(const int* __restrict__ p32) {
    int i = blockIdx.x * 256 + threadIdx.x;           // i < 65536
    int w = p32[2 * i + 1];
    if (__syncthreads_or(w != 0) && threadIdx.x == 0) g_is32 = 1;
}

// ---------------- 0c: decode src/dst to int32 + count dst degrees ------------
__global__ __launch_bounds__(256) void k_decode(const int* __restrict__ p32) {
    int i = blockIdx.x * 256 + threadIdx.x;
    if (i >= N_EDGES) return;
    int s, d;
    if (g_is32) {
        s = p32[i];
        d = p32[N_EDGES + i];
    } else {                                          // int64: low word of each
        s = p32[2 * i];
        d = p32[2 * (N_EDGES + i)];
    }
    g_src[i] = s;
    g_dst[i] = d;
    atomicAdd(&g_deg[d], 1);                          // RED (no return)
}

// ---------------- 1: h = x @ W  (128x128 tile, 8x8 per thread) ---------------
__global__ __launch_bounds__(256) void k_gemm(const float* __restrict__ x,
                                              const float* __restrict__ W) {
    __shared__ float Xs[16][132];    // [k][row], padded
    __shared__ float Ws[16][128];    // [k][col]

    const int tid = threadIdx.x;
    const int tx = tid & 15;         // col group
    const int ty = tid >> 4;         // row group
    const int row0 = blockIdx.x * 128;

    float acc[8][8];
#pragma unroll
    for (int i = 0; i < 8; i++)
#pragma unroll
        for (int j = 0; j < 8; j++) acc[i][j] = 0.0f;

    for (int k0 = 0; k0 < 128; k0 += 16) {
        // load X tile 128x16 (512 float4s), store transposed into Xs[k][row]
#pragma unroll
        for (int t = 0; t < 2; t++) {
            int idx = tid * 2 + t;                 // 0..511
            int r   = idx >> 2;                    // 0..127
            int kq  = idx & 3;                     // 0..3
            float4 v = make_float4(0.f, 0.f, 0.f, 0.f);
            if (row0 + r < N_NODES)
                v = *(const float4*)&x[(size_t)(row0 + r) * 128 + k0 + kq * 4];
            Xs[kq * 4 + 0][r] = v.x;
            Xs[kq * 4 + 1][r] = v.y;
            Xs[kq * 4 + 2][r] = v.z;
            Xs[kq * 4 + 3][r] = v.w;
        }
        // load W tile 16x128 (512 float4s) directly
#pragma unroll
        for (int t = 0; t < 2; t++) {
            int idx = tid * 2 + t;                 // 0..511
            int kk  = idx >> 5;                    // 0..15
            int c4  = idx & 31;                    // 0..31
            *(float4*)&Ws[kk][c4 * 4] = *(const float4*)&W[(k0 + kk) * 128 + c4 * 4];
        }
        __syncthreads();

#pragma unroll
        for (int kk = 0; kk < 16; kk++) {
            float xr[8], wr[8];
            *(float4*)&xr[0] = *(const float4*)&Xs[kk][ty * 8 + 0];
            *(float4*)&xr[4] = *(const float4*)&Xs[kk][ty * 8 + 4];
            *(float4*)&wr[0] = *(const float4*)&Ws[kk][tx * 8 + 0];
            *(float4*)&wr[4] = *(const float4*)&Ws[kk][tx * 8 + 4];
#pragma unroll
            for (int i = 0; i < 8; i++)
#pragma unroll
                for (int j = 0; j < 8; j++)
                    acc[i][j] = fmaf(xr[i], wr[j], acc[i][j]);
        }
        __syncthreads();
    }

#pragma unroll
    for (int i = 0; i < 8; i++) {
        int row = row0 + ty * 8 + i;
        if (row < N_NODES) {
            *(float4*)&g_h[(size_t)row * 128 + tx * 8 + 0] = *(float4*)&acc[i][0];
            *(float4*)&g_h[(size_t)row * 128 + tx * 8 + 4] = *(float4*)&acc[i][4];
        }
    }
}

// ---------------- 2: s1 = h@a1, s2 = h@a2  (warp per node) -------------------
__global__ __launch_bounds__(256) void k_scores(const float* __restrict__ a) {
    int gw   = (blockIdx.x * 256 + threadIdx.x) >> 5;
    int lane = threadIdx.x & 31;
    if (gw >= N_NODES) return;

    const float4 hv = *(const float4*)&g_h[(size_t)gw * 128 + lane * 4];
    const float4 a1 = *(const float4*)&a[lane * 4];
    const float4 a2 = *(const float4*)&a[128 + lane * 4];

    float p1 = hv.x * a1.x + hv.y * a1.y + hv.z * a1.z + hv.w * a1.w;
    float p2 = hv.x * a2.x + hv.y * a2.y + hv.z * a2.z + hv.w * a2.w;
#pragma unroll
    for (int s = 16; s > 0; s >>= 1) {
        p1 += __shfl_xor_sync(0xFFFFFFFFu, p1, s);
        p2 += __shfl_xor_sync(0xFFFFFFFFu, p2, s);
    }
    if (lane == 0) { g_s1[gw] = p1; g_s2[gw] = p2; }
}

// ---------------- 2b: node-score maxima (upper bound for softmax shift) ------
__global__ __launch_bounds__(1024) void k_smax() {
    __shared__ float sm1[1024], sm2[1024];
    int i = blockIdx.x * 1024 + threadIdx.x;
    float v1 = (i < N_NODES) ? g_s1[i] : -1e30f;
    float v2 = (i < N_NODES) ? g_s2[i] : -1e30f;
    sm1[threadIdx.x] = v1; sm2[threadIdx.x] = v2;
    __syncthreads();
    for (int s = 512; s > 0; s >>= 1) {
        if (threadIdx.x < s) {
            sm1[threadIdx.x] = fmaxf(sm1[threadIdx.x], sm1[threadIdx.x + s]);
            sm2[threadIdx.x] = fmaxf(sm2[threadIdx.x], sm2[threadIdx.x + s]);
        }
        __syncthreads();
    }
    if (threadIdx.x == 0) {
        atomicMax(&g_m1enc, f_enc(sm1[0]));
        atomicMax(&g_m2enc, f_enc(sm2[0]));
    }
}

// ---------------- 3: single edge pass: p = exp(lrelu(s1+s2) - C); sum --------
// C = lrelu(max s1 + max s2) >= every edge score (lrelu monotone), and softmax
// is shift-invariant, so any upper bound is a valid stable shift.
__global__ __launch_bounds__(EBLK) void k_edge() {
    __shared__ float sm[EBLK];
    const float m1 = f_dec(g_m1enc), m2 = f_dec(g_m2enc);
    const float mt = m1 + m2;
    const float C  = (mt > 0.0f) ? mt : ALPHA * mt;

    int i = blockIdx.x * EBLK + threadIdx.x;
    float v = 0.0f;
    if (i < N_EDGES) {
        float t = g_s1[g_src[i]] + g_s2[g_dst[i]];
        float e = (t > 0.0f) ? t : ALPHA * t;
        v = __expf(e - C);
        g_e[i] = v;
    }
    sm[threadIdx.x] = v;
    __syncthreads();
    for (int s = EBLK / 2; s > 0; s >>= 1) {
        if (threadIdx.x < s) sm[threadIdx.x] += sm[threadIdx.x + s];
        __syncthreads();
    }
    if (threadIdx.x == 0) g_psum[blockIdx.x] = sm[0];
}

// ---------------- 4: reduce block sums -> g_invsum ---------------------------
__global__ __launch_bounds__(1024) void k_reduce_sum() {
    __shared__ float sm[1024];
    float m = 0.0f;
    for (int i = threadIdx.x; i < NEB; i += 1024) m += g_psum[i];
    sm[threadIdx.x] = m;
    __syncthreads();
    for (int s = 512; s > 0; s >>= 1) {
        if (threadIdx.x < s) sm[threadIdx.x] += sm[threadIdx.x + s];
        __syncthreads();
    }
    if (threadIdx.x == 0) g_invsum = 1.0f / sm[0];
}

// ---------------- 5: two-level exclusive scan of degrees ---------------------
__global__ __launch_bounds__(1024) void k_scan1() {      // 49 blocks
    __shared__ int sm[1024];
    int i = blockIdx.x * 1024 + threadIdx.x;
    int v = (i < N_NODES) ? g_deg[i] : 0;
    sm[threadIdx.x] = v;
    __syncthreads();
    for (int s = 1; s < 1024; s <<= 1) {
        int t = (threadIdx.x >= s) ? sm[threadIdx.x - s] : 0;
        __syncthreads();
        sm[threadIdx.x] += t;
        __syncthreads();
    }
    if (i < N_NODES) g_off[i] = sm[threadIdx.x];         // inclusive (temp)
    if (threadIdx.x == 1023) g_bsum[blockIdx.x] = sm[1023];
}

__global__ void k_scan2() {                              // 1 thread, 49 values
    if (threadIdx.x == 0) {
        int c = 0;
        for (int b = 0; b < (N_NODES + 1023) / 1024; b++) { g_bexc[b] = c; c += g_bsum[b]; }
    }
}

__global__ __launch_bounds__(1024) void k_scan3() {      // 49 blocks
    int i = blockIdx.x * 1024 + threadIdx.x;
    if (i < N_NODES) {
        int excl = g_off[i] - g_deg[i] + g_bexc[blockIdx.x];
        g_off[i] = excl;
        g_cursor[i] = excl;
    }
}

// ---------------- 6: permute edges into dst-sorted CSR -----------------------
__global__ __launch_bounds__(256) void k_permute() {
    int i = blockIdx.x * 256 + threadIdx.x;
    if (i >= N_EDGES) return;
    int d = g_dst[i];
    int pos = atomicAdd(&g_cursor[d], 1);
    int2 ent;
    ent.x = g_src[i];
    ent.y = __float_as_int(g_e[i]);
    g_csr[pos] = ent;
}

// ---------------- 7: gather  out[n] = invsum * sum_j p_j * h[src_j] ----------
__global__ __launch_bounds__(256) void k_gather(float* __restrict__ out) {
    const int warp = threadIdx.x >> 5;
    const int lane = threadIdx.x & 31;
    const int node = blockIdx.x * 8 + warp;
    if (node >= N_NODES) return;

    const int beg = g_off[node];
    const int end = beg + g_deg[node];

    float ax = 0.f, ay = 0.f, az = 0.f, aw = 0.f;
    int j = beg;
    for (; j + 3 < end; j += 4) {                    // 4-way unroll for MLP
#pragma unroll
        for (int u = 0; u < 4; u++) {
            const int2 e = g_csr[j + u];
            const float p = __int_as_float(e.y);
            const float4 v = *(const float4*)&g_h[(size_t)e.x * 128 + lane * 4];
            ax = fmaf(p, v.x, ax); ay = fmaf(p, v.y, ay);
            az = fmaf(p, v.z, az); aw = fmaf(p, v.w, aw);
        }
    }
    for (; j < end; j++) {
        const int2 e = g_csr[j];
        const float p = __int_as_float(e.y);
        const float4 v = *(const float4*)&g_h[(size_t)e.x * 128 + lane * 4];
        ax = fmaf(p, v.x, ax); ay = fmaf(p, v.y, ay);
        az = fmaf(p, v.z, az); aw = fmaf(p, v.w, aw);
    }

    const float inv = g_invsum;
    float4 r; r.x = ax * inv; r.y = ay * inv; r.z = az * inv; r.w = aw * inv;
    *(float4*)&out[(size_t)node * 128 + lane * 4] = r;
}

// ---------------- launch -----------------------------------------------------
extern "C" void kernel_launch(void* const* d_in, const int* in_sizes, int n_in,
                              void* d_out, int out_size) {
    const float* x = nullptr;
    const float* W = nullptr;
    const float* a = nullptr;
    const int*   ei = nullptr;
    for (int i = 0; i < n_in; i++) {
        if (in_sizes[i] == N_NODES * D)      x  = (const float*)d_in[i];
        else if (in_sizes[i] == D * D)       W  = (const float*)d_in[i];
        else if (in_sizes[i] == 2 * D)       a  = (const float*)d_in[i];
        else if (in_sizes[i] == 2 * N_EDGES) ei = (const int*)d_in[i];
    }
    float* out = (float*)d_out;
    const int NB = (N_NODES + 1023) / 1024;          // 49

    k_init<<<NB, 1024>>>();
    k_detect<<<256, 256>>>(ei);                      // samples 65536 odd words
    k_decode<<<(N_EDGES + 255) / 256, 256>>>(ei);
    k_gemm<<<(N_NODES + 127) / 128, 256>>>(x, W);
    k_scores<<<(N_NODES * 32 + 255) / 256, 256>>>(a);
    k_smax<<<NB, 1024>>>();
    k_edge<<<NEB, EBLK>>>();
    k_reduce_sum<<<1, 1024>>>();
    k_scan1<<<NB, 1024>>>();
    k_scan2<<<1, 32>>>();
    k_scan3<<<NB, 1024>>>();
    k_permute<<<(N_EDGES + 255) / 256, 256>>>();
    k_gather<<<(N_NODES + 7) / 8, 256>>>(out);
}

// round 16
// speedup vs baseline: 2.7678x; 1.0846x over previous
#include <cuda_runtime.h>
#include <cuda_fp16.h>
#include <math.h>

#define N_NODES 50000
#define N_EDGES 800000
#define D 128
#define ALPHA 0.2f

// ---------------- scratch (static device globals; no allocation) ------------
__device__ __half g_h16[N_NODES * D];       // 12.8 MB (gather copy of h)
__device__ float g_s1[N_NODES];
__device__ float g_s2[N_NODES];
__device__ int   g_src[N_EDGES];
__device__ int   g_dst[N_EDGES];
__device__ int   g_deg[N_NODES];
__device__ int   g_off[N_NODES];
__device__ int   g_cursor[N_NODES];
__device__ int2  g_csr[N_EDGES];            // {src, float_bits(p)} per dst bucket
__device__ int   g_bsum[64];
__device__ int   g_bexc[64];
__device__ float g_psum[4096];
__device__ float g_invsum;
__device__ int   g_m1enc;                   // encoded float max of s1
__device__ int   g_m2enc;                   // encoded float max of s2
__device__ int   g_is32;                    // 1 if edge_index is int32

static constexpr int EBLK = 256;
static constexpr int NEB  = (N_EDGES + EBLK - 1) / EBLK;   // 3125

// order-preserving float<->int encode (monotone for non-NaN)
__device__ __forceinline__ int   f_enc(float f) { int i = __float_as_int(f); return (i >= 0) ? i : (i ^ 0x7FFFFFFF); }
__device__ __forceinline__ float f_dec(int i)   { return __int_as_float((i >= 0) ? i : (i ^ 0x7FFFFFFF)); }

// ---------------- 0a: init counters ------------------------------------------
__global__ void k_init() {
    int i = blockIdx.x * 1024 + threadIdx.x;
    if (i < N_NODES) g_deg[i] = 0;
    if (i == 0) { g_is32 = 0; g_m1enc = f_enc(-1e30f); g_m2enc = f_enc(-1e30f); }
}

// ---------------- 0b: detect int32 vs int64 (sampled: first 64K odd words) ---
// int64 (LE) indices < 2^31 -> odd 32-bit words all zero; int32 random -> not.
__global__ __launch_bounds__(256) void k_detect(const int* __restrict__ p32) {
    int i = blockIdx.x * 256 + threadIdx.x;           // i < 65536
    int w = p32[2 * i + 1];
    if (__syncthreads_or(w != 0) && threadIdx.x == 0) g_is32 = 1;
}

// ---------------- 0c: decode src/dst to int32 + count dst degrees ------------
__global__ __launch_bounds__(256) void k_decode(const int* __restrict__ p32) {
    int i = blockIdx.x * 256 + threadIdx.x;
    if (i >= N_EDGES) return;
    int s, d;
    if (g_is32) {
        s = p32[i];
        d = p32[N_EDGES + i];
    } else {                                          // int64: low word of each
        s = p32[2 * i];
        d = p32[2 * (N_EDGES + i)];
    }
    g_src[i] = s;
    g_dst[i] = d;
    atomicAdd(&g_deg[d], 1);                          // RED (no return)
}

// ---------------- 1: h = x@W (128x128 tile, 8x8/thread), fused s1/s2 + fp16 h
__global__ __launch_bounds__(256) void k_gemm(const float* __restrict__ x,
                                              const float* __restrict__ W,
                                              const float* __restrict__ a) {
    __shared__ float Xs[16][132];    // [k][row], padded
    __shared__ float Ws[16][128];    // [k][col]

    const int tid = threadIdx.x;
    const int tx = tid & 15;         // col group
    const int ty = tid >> 4;         // row group
    const int row0 = blockIdx.x * 128;

    float acc[8][8];
#pragma unroll
    for (int i = 0; i < 8; i++)
#pragma unroll
        for (int j = 0; j < 8; j++) acc[i][j] = 0.0f;

    for (int k0 = 0; k0 < 128; k0 += 16) {
        // load X tile 128x16 (512 float4s), store transposed into Xs[k][row]
#pragma unroll
        for (int t = 0; t < 2; t++) {
            int idx = tid * 2 + t;                 // 0..511
            int r   = idx >> 2;                    // 0..127
            int kq  = idx & 3;                     // 0..3
            float4 v = make_float4(0.f, 0.f, 0.f, 0.f);
            if (row0 + r < N_NODES)
                v = *(const float4*)&x[(size_t)(row0 + r) * 128 + k0 + kq * 4];
            Xs[kq * 4 + 0][r] = v.x;
            Xs[kq * 4 + 1][r] = v.y;
            Xs[kq * 4 + 2][r] = v.z;
            Xs[kq * 4 + 3][r] = v.w;
        }
        // load W tile 16x128 (512 float4s) directly
#pragma unroll
        for (int t = 0; t < 2; t++) {
            int idx = tid * 2 + t;                 // 0..511
            int kk  = idx >> 5;                    // 0..15
            int c4  = idx & 31;                    // 0..31
            *(float4*)&Ws[kk][c4 * 4] = *(const float4*)&W[(k0 + kk) * 128 + c4 * 4];
        }
        __syncthreads();

#pragma unroll
        for (int kk = 0; kk < 16; kk++) {
            float xr[8], wr[8];
            *(float4*)&xr[0] = *(const float4*)&Xs[kk][ty * 8 + 0];
            *(float4*)&xr[4] = *(const float4*)&Xs[kk][ty * 8 + 4];
            *(float4*)&wr[0] = *(const float4*)&Ws[kk][tx * 8 + 0];
            *(float4*)&wr[4] = *(const float4*)&Ws[kk][tx * 8 + 4];
#pragma unroll
            for (int i = 0; i < 8; i++)
#pragma unroll
                for (int j = 0; j < 8; j++)
                    acc[i][j] = fmaf(xr[i], wr[j], acc[i][j]);
        }
        __syncthreads();
    }

    // epilogue A: store h as fp16 (gather copy) — fp32 h is never materialized
#pragma unroll
    for (int i = 0; i < 8; i++) {
        int row = row0 + ty * 8 + i;
        if (row < N_NODES) {
            __half2 hp[4];
#pragma unroll
            for (int jj = 0; jj < 4; jj++)
                hp[jj] = __floats2half2_rn(acc[i][2 * jj], acc[i][2 * jj + 1]);
            *(uint4*)&g_h16[(size_t)row * 128 + tx * 8] = *(uint4*)hp;
        }
    }

    // epilogue B: s1/s2 from exact fp32 accumulators (half-warp reduction).
    // lanes 0..15 and 16..31 hold tx=0..15 for ty and ty+... (shfl_xor s<16
    // stays within each 16-lane group).
    float a1r[8], a2r[8];
#pragma unroll
    for (int j = 0; j < 8; j++) {
        a1r[j] = __ldg(&a[tx * 8 + j]);
        a2r[j] = __ldg(&a[128 + tx * 8 + j]);
    }
#pragma unroll
    for (int i = 0; i < 8; i++) {
        float p1 = 0.f, p2 = 0.f;
#pragma unroll
        for (int j = 0; j < 8; j++) {
            p1 = fmaf(acc[i][j], a1r[j], p1);
            p2 = fmaf(acc[i][j], a2r[j], p2);
        }
#pragma unroll
        for (int s = 1; s < 16; s <<= 1) {
            p1 += __shfl_xor_sync(0xFFFFFFFFu, p1, s);
            p2 += __shfl_xor_sync(0xFFFFFFFFu, p2, s);
        }
        if (tx == 0) {
            int row = row0 + ty * 8 + i;
            if (row < N_NODES) { g_s1[row] = p1; g_s2[row] = p2; }
        }
    }
}

// ---------------- 2: node-score maxima (upper bound for softmax shift) -------
__global__ __launch_bounds__(1024) void k_smax() {
    __shared__ float sm1[1024], sm2[1024];
    int i = blockIdx.x * 1024 + threadIdx.x;
    float v1 = (i < N_NODES) ? g_s1[i] : -1e30f;
    float v2 = (i < N_NODES) ? g_s2[i] : -1e30f;
    sm1[threadIdx.x] = v1; sm2[threadIdx.x] = v2;
    __syncthreads();
    for (int s = 512; s > 0; s >>= 1) {
        if (threadIdx.x < s) {
            sm1[threadIdx.x] = fmaxf(sm1[threadIdx.x], sm1[threadIdx.x + s]);
            sm2[threadIdx.x] = fmaxf(sm2[threadIdx.x], sm2[threadIdx.x + s]);
        }
        __syncthreads();
    }
    if (threadIdx.x == 0) {
        atomicMax(&g_m1enc, f_enc(sm1[0]));
        atomicMax(&g_m2enc, f_enc(sm2[0]));
    }
}

// ---------------- 3: two-level exclusive scan of degrees ---------------------
__global__ __launch_bounds__(1024) void k_scan1() {      // 49 blocks
    __shared__ int sm[1024];
    int i = blockIdx.x * 1024 + threadIdx.x;
    int v = (i < N_NODES) ? g_deg[i] : 0;
    sm[threadIdx.x] = v;
    __syncthreads();
    for (int s = 1; s < 1024; s <<= 1) {
        int t = (threadIdx.x >= s) ? sm[threadIdx.x - s] : 0;
        __syncthreads();
        sm[threadIdx.x] += t;
        __syncthreads();
    }
    if (i < N_NODES) g_off[i] = sm[threadIdx.x];         // inclusive (temp)
    if (threadIdx.x == 1023) g_bsum[blockIdx.x] = sm[1023];
}

__global__ void k_scan2() {                              // 1 thread, 49 values
    if (threadIdx.x == 0) {
        int c = 0;
        for (int b = 0; b < (N_NODES + 1023) / 1024; b++) { g_bexc[b] = c; c += g_bsum[b]; }
    }
}

__global__ __launch_bounds__(1024) void k_scan3() {      // 49 blocks
    int i = blockIdx.x * 1024 + threadIdx.x;
    if (i < N_NODES) {
        int excl = g_off[i] - g_deg[i] + g_bexc[blockIdx.x];
        g_off[i] = excl;
        g_cursor[i] = excl;
    }
}

// ---------------- 4: fused edge pass: p = exp(lrelu(s1+s2)-C), CSR write, sum
// C = lrelu(max s1 + max s2) >= every edge score (lrelu monotone); softmax is
// shift-invariant so any upper bound is a valid stable shift.
__global__ __launch_bounds__(EBLK) void k_edgeperm() {
    __shared__ float sm[EBLK];
    const float m1 = f_dec(g_m1enc), m2 = f_dec(g_m2enc);
    const float mt = m1 + m2;
    const float C  = (mt > 0.0f) ? mt : ALPHA * mt;

    int i = blockIdx.x * EBLK + threadIdx.x;
    float v = 0.0f;
    if (i < N_EDGES) {
        int s = g_src[i];
        int d = g_dst[i];
        float t = g_s1[s] + g_s2[d];
        float e = (t > 0.0f) ? t : ALPHA * t;
        v = __expf(e - C);
        int pos = atomicAdd(&g_cursor[d], 1);
        int2 ent; ent.x = s; ent.y = __float_as_int(v);
        g_csr[pos] = ent;
    }
    sm[threadIdx.x] = v;
    __syncthreads();
    for (int s = EBLK / 2; s > 0; s >>= 1) {
        if (threadIdx.x < s) sm[threadIdx.x] += sm[threadIdx.x + s];
        __syncthreads();
    }
    if (threadIdx.x == 0) g_psum[blockIdx.x] = sm[0];
}

// ---------------- 5: reduce block sums -> g_invsum ---------------------------
__global__ __launch_bounds__(1024) void k_reduce_sum() {
    __shared__ float sm[1024];
    float m = 0.0f;
    for (int i = threadIdx.x; i < NEB; i += 1024) m += g_psum[i];
    sm[threadIdx.x] = m;
    __syncthreads();
    for (int s = 512; s > 0; s >>= 1) {
        if (threadIdx.x < s) sm[threadIdx.x] += sm[threadIdx.x + s];
        __syncthreads();
    }
    if (threadIdx.x == 0) g_invsum = 1.0f / sm[0];
}

// ---------------- 6: gather  out[n] = invsum * sum_j p_j * h16[src_j] --------
// Warp per node; fp16 h rows (256 B/row), fp32 accumulation.
__global__ __launch_bounds__(256) void k_gather(float* __restrict__ out) {
    const int warp = threadIdx.x >> 5;
    const int lane = threadIdx.x & 31;
    const int node = blockIdx.x * 8 + warp;
    if (node >= N_NODES) return;

    const int beg = g_off[node];
    const int end = beg + g_deg[node];

    float ax = 0.f, ay = 0.f, az = 0.f, aw = 0.f;
    int j = beg;
    for (; j + 3 < end; j += 4) {                    // 4-way unroll for MLP
#pragma unroll
        for (int u = 0; u < 4; u++) {
            const int2 e = g_csr[j + u];
            const float p = __int_as_float(e.y);
            const uint2 raw = *(const uint2*)&g_h16[(size_t)e.x * 128 + lane * 4];
            const float2 f01 = __half22float2(*(const __half2*)&raw.x);
            const float2 f23 = __half22float2(*(const __half2*)&raw.y);
            ax = fmaf(p, f01.x, ax); ay = fmaf(p, f01.y, ay);
            az = fmaf(p, f23.x, az); aw = fmaf(p, f23.y, aw);
        }
    }
    for (; j < end; j++) {
        const int2 e = g_csr[j];
        const float p = __int_as_float(e.y);
        const uint2 raw = *(const uint2*)&g_h16[(size_t)e.x * 128 + lane * 4];
        const float2 f01 = __half22float2(*(const __half2*)&raw.x);
        const float2 f23 = __half22float2(*(const __half2*)&raw.y);
        ax = fmaf(p, f01.x, ax); ay = fmaf(p, f01.y, ay);
        az = fmaf(p, f23.x, az); aw = fmaf(p, f23.y, aw);
    }

    const float inv = g_invsum;
    float4 r; r.x = ax * inv; r.y = ay * inv; r.z = az * inv; r.w = aw * inv;
    *(float4*)&out[(size_t)node * 128 + lane * 4] = r;
}

// ---------------- launch -----------------------------------------------------
extern "C" void kernel_launch(void* const* d_in, const int* in_sizes, int n_in,
                              void* d_out, int out_size) {
    const float* x = nullptr;
    const float* W = nullptr;
    const float* a = nullptr;
    const int*   ei = nullptr;
    for (int i = 0; i < n_in; i++) {
        if (in_sizes[i] == N_NODES * D)      x  = (const float*)d_in[i];
        else if (in_sizes[i] == D * D)       W  = (const float*)d_in[i];
        else if (in_sizes[i] == 2 * D)       a  = (const float*)d_in[i];
        else if (in_sizes[i] == 2 * N_EDGES) ei = (const int*)d_in[i];
    }
    float* out = (float*)d_out;
    const int NB = (N_NODES + 1023) / 1024;          // 49

    k_init<<<NB, 1024>>>();
    k_detect<<<256, 256>>>(ei);                      // samples 65536 odd words
    k_decode<<<(N_EDGES + 255) / 256, 256>>>(ei);
    k_gemm<<<(N_NODES + 127) / 128, 256>>>(x, W, a);
    k_smax<<<NB, 1024>>>();
    k_scan1<<<NB, 1024>>>();
    k_scan2<<<1, 32>>>();
    k_scan3<<<NB, 1024>>>();
    k_edgeperm<<<NEB, EBLK>>>();
    k_reduce_sum<<<1, 1024>>>();
    k_gather<<<(N_NODES + 7) / 8, 256>>>(out);
}

// round 17
// speedup vs baseline: 4.1507x; 1.4996x over previous
#include <cuda_runtime.h>
#include <cuda_fp16.h>
#include <math.h>

#define N_NODES 50000
#define N_EDGES 800000
#define D 128
#define ALPHA 0.2f

// ---------------- scratch (static device globals; no allocation) ------------
__device__ __half g_h16[N_NODES * D];       // 12.8 MB (gather copy of h)
__device__ __half g_W16T[D * D];            // W transposed (n-major), fp16
__device__ float g_s1[N_NODES];
__device__ float g_s2[N_NODES];
__device__ int   g_src[N_EDGES];
__device__ int   g_dst[N_EDGES];
__device__ int   g_deg[N_NODES];
__device__ int   g_off[N_NODES];
__device__ int   g_cursor[N_NODES];
__device__ int2  g_csr[N_EDGES];            // {src, float_bits(p)} per dst bucket
__device__ int   g_bsum[64];
__device__ int   g_bexc[64];
__device__ float g_psum[4096];
__device__ float g_invsum;
__device__ int   g_m1enc;                   // encoded float max of s1
__device__ int   g_m2enc;                   // encoded float max of s2
__device__ int   g_is32;                    // 1 if edge_index is int32

static constexpr int EBLK = 256;
static constexpr int NEB  = (N_EDGES + EBLK - 1) / EBLK;   // 3125

// order-preserving float<->int encode (monotone for non-NaN)
__device__ __forceinline__ int   f_enc(float f) { int i = __float_as_int(f); return (i >= 0) ? i : (i ^ 0x7FFFFFFF); }
__device__ __forceinline__ float f_dec(int i)   { return __int_as_float((i >= 0) ? i : (i ^ 0x7FFFFFFF)); }

__device__ __forceinline__ void mma16816(float* c, const unsigned* A,
                                         unsigned b0, unsigned b1) {
    asm volatile(
        "mma.sync.aligned.m16n8k16.row.col.f32.f16.f16.f32 "
        "{%0,%1,%2,%3}, {%4,%5,%6,%7}, {%8,%9}, {%0,%1,%2,%3};\n"
        : "+f"(c[0]), "+f"(c[1]), "+f"(c[2]), "+f"(c[3])
        : "r"(A[0]), "r"(A[1]), "r"(A[2]), "r"(A[3]), "r"(b0), "r"(b1));
}

// ---------------- 0a: init counters + zero score accumulators ----------------
__global__ void k_init() {
    int i = blockIdx.x * 1024 + threadIdx.x;
    if (i < N_NODES) { g_deg[i] = 0; g_s1[i] = 0.0f; g_s2[i] = 0.0f; }
    if (i == 0) { g_is32 = 0; g_m1enc = f_enc(-1e30f); g_m2enc = f_enc(-1e30f); }
}

// ---------------- 0b: detect int32 vs int64 (sampled: first 64K odd words) ---
__global__ __launch_bounds__(256) void k_detect(const int* __restrict__ p32) {
    int i = blockIdx.x * 256 + threadIdx.x;           // i < 65536
    int w = p32[2 * i + 1];
    if (__syncthreads_or(w != 0) && threadIdx.x == 0) g_is32 = 1;
}

// ---------------- 0c: decode src/dst to int32 + count dst degrees ------------
__global__ __launch_bounds__(256) void k_decode(const int* __restrict__ p32) {
    int i = blockIdx.x * 256 + threadIdx.x;
    if (i >= N_EDGES) return;
    int s, d;
    if (g_is32) {
        s = p32[i];
        d = p32[N_EDGES + i];
    } else {                                          // int64: low word of each
        s = p32[2 * i];
        d = p32[2 * (N_EDGES + i)];
    }
    g_src[i] = s;
    g_dst[i] = d;
    atomicAdd(&g_deg[d], 1);                          // RED (no return)
}

// ---------------- 0d: W -> fp16, transposed to n-major -----------------------
__global__ __launch_bounds__(256) void k_wprep(const float* __restrict__ W) {
    int idx = blockIdx.x * 256 + threadIdx.x;         // 0..16383
    int n = idx >> 7, k = idx & 127;
    g_W16T[n * 128 + k] = __float2half(W[k * 128 + n]);
}

// ---------------- 1: h = x@W via HMMA m16n8k16; fused s1/s2 + fp16 h ---------
// Block: 128 rows x 128 cols, 8 warps (4 row-groups x 2 col-groups).
// Per warp: 32 rows x 64 cols = 2 x 8 mma tiles; K in 2 smem chunks of 64.
__global__ __launch_bounds__(256) void k_gemm(const float* __restrict__ x,
                                              const float* __restrict__ a) {
    __shared__ __half Xs[128 * 72];   // [row][k], stride 72 (pad 8)
    __shared__ __half Ws[128 * 72];   // [n][k],   stride 72

    const int tid  = threadIdx.x;
    const int lane = tid & 31;
    const int warp = tid >> 5;
    const int wm   = warp & 3;        // row group (32 rows)
    const int wn   = warp >> 2;       // col group (64 cols)
    const int g    = lane >> 2;       // 0..7
    const int t    = lane & 3;        // 0..3
    const int row0 = blockIdx.x * 128;

    float acc[2][8][4];
#pragma unroll
    for (int mi = 0; mi < 2; mi++)
#pragma unroll
        for (int ni = 0; ni < 8; ni++)
#pragma unroll
            for (int q = 0; q < 4; q++) acc[mi][ni][q] = 0.0f;

    for (int kc = 0; kc < 2; kc++) {
        const int k0 = kc * 64;
        // X tile: 128 rows x 64 k, fp32 -> fp16 (2048 float4s)
#pragma unroll
        for (int i = 0; i < 8; i++) {
            int idx = tid + i * 256;
            int r   = idx >> 4;                    // 0..127
            int c4  = idx & 15;                    // float4 within 64
            float4 v = make_float4(0.f, 0.f, 0.f, 0.f);
            if (row0 + r < N_NODES)
                v = *(const float4*)&x[(size_t)(row0 + r) * 128 + k0 + c4 * 4];
            __half2 h0 = __floats2half2_rn(v.x, v.y);
            __half2 h1 = __floats2half2_rn(v.z, v.w);
            uint2 pk; pk.x = *(unsigned*)&h0; pk.y = *(unsigned*)&h1;
            *(uint2*)&Xs[r * 72 + c4 * 4] = pk;
        }
        // W tile from prepped fp16 transpose: 128 n x 64 k (1024 uint4s)
#pragma unroll
        for (int i = 0; i < 4; i++) {
            int idx = tid + i * 256;
            int n   = idx >> 3;
            int k8  = idx & 7;
            uint4 v = *(const uint4*)&g_W16T[n * 128 + k0 + k8 * 8];
            *(uint4*)&Ws[n * 72 + k8 * 8] = v;
        }
        __syncthreads();

#pragma unroll
        for (int ks = 0; ks < 4; ks++) {
            const int cc = ks * 16 + 2 * t;
            unsigned A[2][4];
#pragma unroll
            for (int mi = 0; mi < 2; mi++) {
                int r = wm * 32 + mi * 16 + g;
                A[mi][0] = *(const unsigned*)&Xs[r * 72 + cc];
                A[mi][1] = *(const unsigned*)&Xs[(r + 8) * 72 + cc];
                A[mi][2] = *(const unsigned*)&Xs[r * 72 + cc + 8];
                A[mi][3] = *(const unsigned*)&Xs[(r + 8) * 72 + cc + 8];
            }
#pragma unroll
            for (int ni = 0; ni < 8; ni++) {
                int n = wn * 64 + ni * 8 + g;
                unsigned b0 = *(const unsigned*)&Ws[n * 72 + cc];
                unsigned b1 = *(const unsigned*)&Ws[n * 72 + cc + 8];
                mma16816(acc[0][ni], A[0], b0, b1);
                mma16816(acc[1][ni], A[1], b0, b1);
            }
        }
        __syncthreads();
    }

    // epilogue A: h as fp16 (c0,c1 = row rb, cols 2t,2t+1; c2,c3 = row rb+8)
#pragma unroll
    for (int mi = 0; mi < 2; mi++) {
        int rb = row0 + wm * 32 + mi * 16 + g;
#pragma unroll
        for (int ni = 0; ni < 8; ni++) {
            int c = wn * 64 + ni * 8 + 2 * t;
            if (rb < N_NODES)
                *(__half2*)&g_h16[(size_t)rb * 128 + c] =
                    __floats2half2_rn(acc[mi][ni][0], acc[mi][ni][1]);
            if (rb + 8 < N_NODES)
                *(__half2*)&g_h16[(size_t)(rb + 8) * 128 + c] =
                    __floats2half2_rn(acc[mi][ni][2], acc[mi][ni][3]);
        }
    }

    // epilogue B: s1/s2 partials from exact fp32 accumulators.
#pragma unroll
    for (int mi = 0; mi < 2; mi++) {
        float s1lo = 0.f, s1hi = 0.f, s2lo = 0.f, s2hi = 0.f;
#pragma unroll
        for (int ni = 0; ni < 8; ni++) {
            int c = wn * 64 + ni * 8 + 2 * t;
            float a10 = __ldg(&a[c]),       a11 = __ldg(&a[c + 1]);
            float a20 = __ldg(&a[128 + c]), a21 = __ldg(&a[128 + c + 1]);
            s1lo = fmaf(acc[mi][ni][0], a10, fmaf(acc[mi][ni][1], a11, s1lo));
            s1hi = fmaf(acc[mi][ni][2], a10, fmaf(acc[mi][ni][3], a11, s1hi));
            s2lo = fmaf(acc[mi][ni][0], a20, fmaf(acc[mi][ni][1], a21, s2lo));
            s2hi = fmaf(acc[mi][ni][2], a20, fmaf(acc[mi][ni][3], a21, s2hi));
        }
#pragma unroll
        for (int s = 1; s < 4; s <<= 1) {           // reduce over t (quad)
            s1lo += __shfl_xor_sync(0xFFFFFFFFu, s1lo, s);
            s1hi += __shfl_xor_sync(0xFFFFFFFFu, s1hi, s);
            s2lo += __shfl_xor_sync(0xFFFFFFFFu, s2lo, s);
            s2hi += __shfl_xor_sync(0xFFFFFFFFu, s2hi, s);
        }
        if (t == 0) {
            int rb = row0 + wm * 32 + mi * 16 + g;
            if (rb < N_NODES)     { atomicAdd(&g_s1[rb], s1lo);     atomicAdd(&g_s2[rb], s2lo); }
            if (rb + 8 < N_NODES) { atomicAdd(&g_s1[rb + 8], s1hi); atomicAdd(&g_s2[rb + 8], s2hi); }
        }
    }
}

// ---------------- 2: node-score maxima (upper bound for softmax shift) -------
__global__ __launch_bounds__(1024) void k_smax() {
    __shared__ float sm1[1024], sm2[1024];
    int i = blockIdx.x * 1024 + threadIdx.x;
    float v1 = (i < N_NODES) ? g_s1[i] : -1e30f;
    float v2 = (i < N_NODES) ? g_s2[i] : -1e30f;
    sm1[threadIdx.x] = v1; sm2[threadIdx.x] = v2;
    __syncthreads();
    for (int s = 512; s > 0; s >>= 1) {
        if (threadIdx.x < s) {
            sm1[threadIdx.x] = fmaxf(sm1[threadIdx.x], sm1[threadIdx.x + s]);
            sm2[threadIdx.x] = fmaxf(sm2[threadIdx.x], sm2[threadIdx.x + s]);
        }
        __syncthreads();
    }
    if (threadIdx.x == 0) {
        atomicMax(&g_m1enc, f_enc(sm1[0]));
        atomicMax(&g_m2enc, f_enc(sm2[0]));
    }
}

// ---------------- 3: two-level exclusive scan of degrees ---------------------
__global__ __launch_bounds__(1024) void k_scan1() {      // 49 blocks
    __shared__ int sm[1024];
    int i = blockIdx.x * 1024 + threadIdx.x;
    int v = (i < N_NODES) ? g_deg[i] : 0;
    sm[threadIdx.x] = v;
    __syncthreads();
    for (int s = 1; s < 1024; s <<= 1) {
        int t = (threadIdx.x >= s) ? sm[threadIdx.x - s] : 0;
        __syncthreads();
        sm[threadIdx.x] += t;
        __syncthreads();
    }
    if (i < N_NODES) g_off[i] = sm[threadIdx.x];         // inclusive (temp)
    if (threadIdx.x == 1023) g_bsum[blockIdx.x] = sm[1023];
}

__global__ void k_scan2() {                              // 1 thread, 49 values
    if (threadIdx.x == 0) {
        int c = 0;
        for (int b = 0; b < (N_NODES + 1023) / 1024; b++) { g_bexc[b] = c; c += g_bsum[b]; }
    }
}

__global__ __launch_bounds__(1024) void k_scan3() {      // 49 blocks
    int i = blockIdx.x * 1024 + threadIdx.x;
    if (i < N_NODES) {
        int excl = g_off[i] - g_deg[i] + g_bexc[blockIdx.x];
        g_off[i] = excl;
        g_cursor[i] = excl;
    }
}

// ---------------- 4: fused edge pass: p = exp(lrelu(s1+s2)-C), CSR write, sum
__global__ __launch_bounds__(EBLK) void k_edgeperm() {
    __shared__ float sm[EBLK];
    const float m1 = f_dec(g_m1enc), m2 = f_dec(g_m2enc);
    const float mt = m1 + m2;
    const float C  = (mt > 0.0f) ? mt : ALPHA * mt;

    int i = blockIdx.x * EBLK + threadIdx.x;
    float v = 0.0f;
    if (i < N_EDGES) {
        int s = g_src[i];
        int d = g_dst[i];
        float t = g_s1[s] + g_s2[d];
        float e = (t > 0.0f) ? t : ALPHA * t;
        v = __expf(e - C);
        int pos = atomicAdd(&g_cursor[d], 1);
        int2 ent; ent.x = s; ent.y = __float_as_int(v);
        g_csr[pos] = ent;
    }
    sm[threadIdx.x] = v;
    __syncthreads();
    for (int s = EBLK / 2; s > 0; s >>= 1) {
        if (threadIdx.x < s) sm[threadIdx.x] += sm[threadIdx.x + s];
        __syncthreads();
    }
    if (threadIdx.x == 0) g_psum[blockIdx.x] = sm[0];
}

// ---------------- 5: reduce block sums -> g_invsum ---------------------------
__global__ __launch_bounds__(1024) void k_reduce_sum() {
    __shared__ float sm[1024];
    float m = 0.0f;
    for (int i = threadIdx.x; i < NEB; i += 1024) m += g_psum[i];
    sm[threadIdx.x] = m;
    __syncthreads();
    for (int s = 512; s > 0; s >>= 1) {
        if (threadIdx.x < s) sm[threadIdx.x] += sm[threadIdx.x + s];
        __syncthreads();
    }
    if (threadIdx.x == 0) g_invsum = 1.0f / sm[0];
}

// ---------------- 6: gather  out[n] = invsum * sum_j p_j * h16[src_j] --------
__global__ __launch_bounds__(256) void k_gather(float* __restrict__ out) {
    const int warp = threadIdx.x >> 5;
    const int lane = threadIdx.x & 31;
    const int node = blockIdx.x * 8 + warp;
    if (node >= N_NODES) return;

    const int beg = g_off[node];
    const int end = beg + g_deg[node];

    float ax = 0.f, ay = 0.f, az = 0.f, aw = 0.f;
    int j = beg;
    for (; j + 3 < end; j += 4) {                    // 4-way unroll for MLP
#pragma unroll
        for (int u = 0; u < 4; u++) {
            const int2 e = g_csr[j + u];
            const float p = __int_as_float(e.y);
            const uint2 raw = *(const uint2*)&g_h16[(size_t)e.x * 128 + lane * 4];
            const float2 f01 = __half22float2(*(const __half2*)&raw.x);
            const float2 f23 = __half22float2(*(const __half2*)&raw.y);
            ax = fmaf(p, f01.x, ax); ay = fmaf(p, f01.y, ay);
            az = fmaf(p, f23.x, az); aw = fmaf(p, f23.y, aw);
        }
    }
    for (; j < end; j++) {
        const int2 e = g_csr[j];
        const float p = __int_as_float(e.y);
        const uint2 raw = *(const uint2*)&g_h16[(size_t)e.x * 128 + lane * 4];
        const float2 f01 = __half22float2(*(const __half2*)&raw.x);
        const float2 f23 = __half22float2(*(const __half2*)&raw.y);
        ax = fmaf(p, f01.x, ax); ay = fmaf(p, f01.y, ay);
        az = fmaf(p, f23.x, az); aw = fmaf(p, f23.y, aw);
    }

    const float inv = g_invsum;
    float4 r; r.x = ax * inv; r.y = ay * inv; r.z = az * inv; r.w = aw * inv;
    *(float4*)&out[(size_t)node * 128 + lane * 4] = r;
}

// ---------------- launch -----------------------------------------------------
extern "C" void kernel_launch(void* const* d_in, const int* in_sizes, int n_in,
                              void* d_out, int out_size) {
    const float* x = nullptr;
    const float* W = nullptr;
    const float* a = nullptr;
    const int*   ei = nullptr;
    for (int i = 0; i < n_in; i++) {
        if (in_sizes[i] == N_NODES * D)      x  = (const float*)d_in[i];
        else if (in_sizes[i] == D * D)       W  = (const float*)d_in[i];
        else if (in_sizes[i] == 2 * D)       a  = (const float*)d_in[i];
        else if (in_sizes[i] == 2 * N_EDGES) ei = (const int*)d_in[i];
    }
    float* out = (float*)d_out;
    const int NB = (N_NODES + 1023) / 1024;          // 49

    k_init<<<NB, 1024>>>();
    k_detect<<<256, 256>>>(ei);                      // samples 65536 odd words
    k_decode<<<(N_EDGES + 255) / 256, 256>>>(ei);
    k_wprep<<<64, 256>>>(W);
    k_gemm<<<(N_NODES + 127) / 128, 256>>>(x, a);
    k_smax<<<NB, 1024>>>();
    k_scan1<<<NB, 1024>>>();
    k_scan2<<<1, 32>>>();
    k_scan3<<<NB, 1024>>>();
    k_edgeperm<<<NEB, EBLK>>>();
    k_reduce_sum<<<1, 1024>>>();
    k_gather<<<(N_NODES + 7) / 8, 256>>>(out);
}